// round 15
// baseline (speedup 1.0000x reference)
#include <cuda_runtime.h>
#include <cuda_fp16.h>

#define L_FRAMES 16
#define C_CH     16
#define H_DIM    128
#define W_DIM    256
#define HW       (H_DIM * W_DIM)
#define DECAY_F  0.1f
#define FRAME_BYTES (HW * 32)          // one fp16 channel-last frame = 1 MB

// Channel-last fp16 scratch: [k][h][w][c], 16 MB (single copy)
__device__ __half g_imgT[L_FRAMES * HW * C_CH];

// ---------------------------------------------------------------------------
// Prep: transpose img [k][c][h][w] fp32 -> [k][h][w][c] fp16.
// ---------------------------------------------------------------------------
__global__ void prep_kernel(const float* __restrict__ img) {
    const int kh = blockIdx.x;          // k*H + h
    const int w  = threadIdx.x;         // 0..255
    const int k  = kh >> 7;
    const int h  = kh & (H_DIM - 1);

    __half2 v[8];
#pragma unroll
    for (int c = 0; c < 8; c++) {
        float a = img[((k * C_CH + 2 * c + 0) * H_DIM + h) * W_DIM + w];
        float b = img[((k * C_CH + 2 * c + 1) * H_DIM + h) * W_DIM + w];
        v[c] = __floats2half2_rn(a, b);
    }
    uint4* dst = reinterpret_cast<uint4*>(&g_imgT[((size_t)kh * W_DIM + w) * C_CH]);
    dst[0] = *reinterpret_cast<const uint4*>(&v[0]);
    dst[1] = *reinterpret_cast<const uint4*>(&v[4]);
}

// ---------------------------------------------------------------------------
// Warped accumulation. Flat grid 8192: t = bx & 15, pixel block = bx >> 4.
// 4 lanes per pixel: ch = sub&1 (16B channel half), xh = sub>>1 (x tap).
// k == t is the identity term (gx = base exactly, weight = 1): handled by a
// coalesced fp32 read of img[t] folded into the store — the gather loop runs
// only k = 0..t-1. Flow staged in SMEM; k in pairs with fp16 pair-accum.
// ---------------------------------------------------------------------------
__global__ void __launch_bounds__(256) sample_kernel(
    const float* __restrict__ img,        // [k][c][h][w] fp32 (diagonal term)
    const float* __restrict__ cum_flow,   // [k][2][h][w]
    const float* __restrict__ mask,       // [t][k]
    const float* __restrict__ dist,       // [t][k]
    float* __restrict__ out)              // [t][c][h][w]
{
    const int t  = blockIdx.x & 15;
    const int p0 = (blockIdx.x >> 4) << 6;

    __shared__ float  ws[L_FRAMES];
    __shared__ float2 sflow[L_FRAMES * 64];   // [k][px], 8 KB

    if (threadIdx.x < L_FRAMES) {
        int i = t * L_FRAMES + threadIdx.x;
        ws[threadIdx.x] = mask[i] * expf(-DECAY_F * dist[i]);
    }
#pragma unroll
    for (int i = 0; i < 4; i++) {
        const int idx = threadIdx.x + i * 256;      // k*64 + px
        const int kk  = idx >> 6;
        const int px  = idx & 63;
        const float fx = cum_flow[(kk * 2 + 0) * HW + p0 + px];
        const float fy = cum_flow[(kk * 2 + 1) * HW + p0 + px];
        sflow[idx] = make_float2(fx, fy);
    }
    __syncthreads();

    const int tid = threadIdx.x;
    const int sub = tid & 3;
    const int ch  = sub & 1;        // channel half: channels [ch*8, ch*8+8)
    const int xh  = sub >> 1;       // x tap: 0 -> x0, 1 -> x0+1
    const int px  = tid >> 2;       // pixel-in-block 0..63
    const int p   = p0 + px;
    const int h   = p >> 8;
    const int w   = p & (W_DIM - 1);

    const float2 ft = sflow[t * 64 + px];

    const float base_x = (float)w * (2.0f / W_DIM) - 1.0f + (1.0f / W_DIM);
    const float base_y = (float)h * (2.0f / H_DIM) - 1.0f + (1.0f / H_DIM);
    const float Ax = (base_x + ft.x + 1.0f) * (W_DIM * 0.5f) - 0.5f;
    const float Ay = (base_y + ft.y + 1.0f) * (H_DIM * 0.5f) - 0.5f;

    const float sx = xh ? 1.0f : -1.0f;
    const float cx = xh ? 0.0f : 1.0f;

    float acc[8];
#pragma unroll
    for (int j = 0; j < 8; j++) acc[j] = 0.0f;

    const char* __restrict__ gbase =
        reinterpret_cast<const char*>(g_imgT) + ch * 16;

    // offsets within the CURRENT frame only (no k term)
#define COORDS(kk, OFF0, OFF1, W0H, W1H)                                       \
    unsigned OFF0, OFF1; __half2 W0H, W1H;                                     \
    {                                                                          \
        const float wk  = ws[(kk)];                                            \
        const float2 fk = sflow[(kk) * 64 + px];                               \
        const float ix = fmaf(-(W_DIM * 0.5f), fk.x, Ax);                      \
        const float iy = fmaf(-(H_DIM * 0.5f), fk.y, Ay);                      \
        const int x0 = __float2int_rd(ix);                                     \
        const int y0 = __float2int_rd(iy);                                     \
        const float wx = ix - (float)x0;                                       \
        const float wy = iy - (float)y0;                                       \
        const int x   = (x0 + xh) & (W_DIM - 1);                               \
        const int y0c = min(max(y0, 0), H_DIM - 1);                            \
        const int y1c = min(max(y0 + 1, 0), H_DIM - 1);                        \
        const float xw = fmaf(sx, wx, cx);                                     \
        const float tw = wk * xw;                                              \
        const float w1 = tw * wy;                                              \
        const float w0 = tw - w1;                                              \
        W0H = __float2half2_rn(w0);                                            \
        W1H = __float2half2_rn(w1);                                            \
        const unsigned ox = (unsigned)x << 5;                                  \
        OFF0 = ox + ((unsigned)y0c << 13);                                     \
        OFF1 = ox + ((unsigned)y1c << 13);                                     \
    }

#define BODY1(kk, GB)                                                          \
    {                                                                          \
        COORDS(kk, o0, o1, w0h, w1h);                                          \
        const uint4 u0 = *reinterpret_cast<const uint4*>((GB) + o0);           \
        const uint4 u1 = *reinterpret_cast<const uint4*>((GB) + o1);           \
        const __half2* h0 = reinterpret_cast<const __half2*>(&u0);             \
        const __half2* h1 = reinterpret_cast<const __half2*>(&u1);             \
        _Pragma("unroll")                                                      \
        for (int j = 0; j < 4; j++) {                                          \
            __half2 s = __hmul2(h0[j], w0h);                                   \
            s = __hfma2(h1[j], w1h, s);                                        \
            const float2 f = __half22float2(s);                                \
            acc[2 * j + 0] += f.x;                                             \
            acc[2 * j + 1] += f.y;                                             \
        }                                                                      \
    }

    // two k's at frames GB, GB+FRAME_BYTES: fp16 pair-accumulation
#define BODY2(kk, GB)                                                          \
    {                                                                          \
        COORDS((kk) + 0, a0, a1, aw0, aw1);                                    \
        const uint4 ua0 = *reinterpret_cast<const uint4*>((GB) + a0);          \
        const uint4 ua1 = *reinterpret_cast<const uint4*>((GB) + a1);          \
        COORDS((kk) + 1, b0, b1, bw0, bw1);                                    \
        const uint4 ub0 = *reinterpret_cast<const uint4*>((GB) + FRAME_BYTES + b0); \
        const uint4 ub1 = *reinterpret_cast<const uint4*>((GB) + FRAME_BYTES + b1); \
        const __half2* ha0 = reinterpret_cast<const __half2*>(&ua0);           \
        const __half2* ha1 = reinterpret_cast<const __half2*>(&ua1);           \
        const __half2* hb0 = reinterpret_cast<const __half2*>(&ub0);           \
        const __half2* hb1 = reinterpret_cast<const __half2*>(&ub1);           \
        _Pragma("unroll")                                                      \
        for (int j = 0; j < 4; j++) {                                          \
            __half2 s = __hmul2(ha0[j], aw0);                                  \
            s = __hfma2(ha1[j], aw1, s);                                       \
            s = __hfma2(hb0[j], bw0, s);                                       \
            s = __hfma2(hb1[j], bw1, s);                                       \
            const float2 f = __half22float2(s);                                \
            acc[2 * j + 0] += f.x;                                             \
            acc[2 * j + 1] += f.y;                                             \
        }                                                                      \
    }

    // gather loop over k = 0..t-1 (k == t handled as exact identity below)
    int k = 0;
#pragma unroll 2
    for (; k + 1 < t; k += 2) {
        BODY2(k, gbase);
        gbase += 2 * FRAME_BYTES;
    }
    if (k < t) BODY1(k, gbase);
#undef BODY2
#undef BODY1
#undef COORDS

    // merge x-halves: partner lane differs in bit 1 of tid
#pragma unroll
    for (int j = 0; j < 8; j++)
        acc[j] += __shfl_xor_sync(0xffffffffu, acc[j], 2);

    // diagonal term (k == t, weight 1, exact position) + store.
    // each lane covers channels [ch*8 + xh*4, +4) at pixel p.
    const int cbase = (t * C_CH + ch * 8 + xh * 4) * HW + p;
#pragma unroll
    for (int j = 0; j < 4; j++)
        out[cbase + j * HW] = acc[xh * 4 + j] + img[cbase + j * HW];
}

extern "C" void kernel_launch(void* const* d_in, const int* in_sizes, int n_in,
                              void* d_out, int out_size) {
    const float* img      = (const float*)d_in[0];  // (1,16,16,128,256)
    const float* cum_flow = (const float*)d_in[1];  // (1,16,2,128,256)
    const float* mask     = (const float*)d_in[2];  // (16,16)
    const float* dist     = (const float*)d_in[3];  // (16,16)
    float* out            = (float*)d_out;          // (1,16,16,128,256)

    prep_kernel<<<L_FRAMES * H_DIM, W_DIM>>>(img);

    sample_kernel<<<HW / 64 * L_FRAMES, 256>>>(img, cum_flow, mask, dist, out);
}

// round 16
// speedup vs baseline: 1.0463x; 1.0463x over previous
#include <cuda_runtime.h>
#include <cuda_fp16.h>

#define L_FRAMES 16
#define C_CH     16
#define H_DIM    128
#define W_DIM    256
#define HW       (H_DIM * W_DIM)
#define DECAY_F  0.1f
#define FRAME_BYTES (HW * 32)          // one fp16 channel-last frame = 1 MB

// Channel-last fp16 scratch: [k][h][w][c], 16 MB (single copy)
__device__ __half g_imgT[L_FRAMES * HW * C_CH];

// ---------------------------------------------------------------------------
// Prep: transpose img [k][c][h][w] fp32 -> [k][h][w][c] fp16.
// ---------------------------------------------------------------------------
__global__ void prep_kernel(const float* __restrict__ img) {
    const int kh = blockIdx.x;          // k*H + h
    const int w  = threadIdx.x;         // 0..255
    const int k  = kh >> 7;
    const int h  = kh & (H_DIM - 1);

    __half2 v[8];
#pragma unroll
    for (int c = 0; c < 8; c++) {
        float a = img[((k * C_CH + 2 * c + 0) * H_DIM + h) * W_DIM + w];
        float b = img[((k * C_CH + 2 * c + 1) * H_DIM + h) * W_DIM + w];
        v[c] = __floats2half2_rn(a, b);
    }
    uint4* dst = reinterpret_cast<uint4*>(&g_imgT[((size_t)kh * W_DIM + w) * C_CH]);
    dst[0] = *reinterpret_cast<const uint4*>(&v[0]);
    dst[1] = *reinterpret_cast<const uint4*>(&v[4]);
}

// ---------------------------------------------------------------------------
// Warped accumulation. Flat grid 8192: t = bx & 15, pixel block = bx >> 4.
// 4 lanes per pixel: ch = sub&1 (16B channel half), xh = sub>>1 (x tap).
// k == t is the identity term (exact position, weight 1): read directly from
// the fp16 scratch at slot p (coalesced, 2 lines/warp) and folded into the
// store — the gather loop runs only k = 0..t-1.
// Flow staged in SMEM; k in pairs with fp16 pair-accumulation.
// ---------------------------------------------------------------------------
__global__ void __launch_bounds__(256) sample_kernel(
    const float* __restrict__ cum_flow,   // [k][2][h][w]
    const float* __restrict__ mask,       // [t][k]
    const float* __restrict__ dist,       // [t][k]
    float* __restrict__ out)              // [t][c][h][w]
{
    const int t  = blockIdx.x & 15;
    const int p0 = (blockIdx.x >> 4) << 6;

    __shared__ float  ws[L_FRAMES];
    __shared__ float2 sflow[L_FRAMES * 64];   // [k][px], 8 KB

    if (threadIdx.x < L_FRAMES) {
        int i = t * L_FRAMES + threadIdx.x;
        ws[threadIdx.x] = mask[i] * expf(-DECAY_F * dist[i]);
    }
#pragma unroll
    for (int i = 0; i < 4; i++) {
        const int idx = threadIdx.x + i * 256;      // k*64 + px
        const int kk  = idx >> 6;
        const int px  = idx & 63;
        const float fx = cum_flow[(kk * 2 + 0) * HW + p0 + px];
        const float fy = cum_flow[(kk * 2 + 1) * HW + p0 + px];
        sflow[idx] = make_float2(fx, fy);
    }
    __syncthreads();

    const int tid = threadIdx.x;
    const int sub = tid & 3;
    const int ch  = sub & 1;        // channel half: channels [ch*8, ch*8+8)
    const int xh  = sub >> 1;       // x tap: 0 -> x0, 1 -> x0+1
    const int px  = tid >> 2;       // pixel-in-block 0..63
    const int p   = p0 + px;
    const int h   = p >> 8;
    const int w   = p & (W_DIM - 1);

    const float2 ft = sflow[t * 64 + px];

    const float base_x = (float)w * (2.0f / W_DIM) - 1.0f + (1.0f / W_DIM);
    const float base_y = (float)h * (2.0f / H_DIM) - 1.0f + (1.0f / H_DIM);
    const float Ax = (base_x + ft.x + 1.0f) * (W_DIM * 0.5f) - 0.5f;
    const float Ay = (base_y + ft.y + 1.0f) * (H_DIM * 0.5f) - 0.5f;

    const float sx = xh ? 1.0f : -1.0f;
    const float cx = xh ? 0.0f : 1.0f;

    float acc[8];
#pragma unroll
    for (int j = 0; j < 8; j++) acc[j] = 0.0f;

    const char* __restrict__ gbase =
        reinterpret_cast<const char*>(g_imgT) + ch * 16;

    // offsets within the CURRENT frame only (no k term)
#define COORDS(kk, OFF0, OFF1, W0H, W1H)                                       \
    unsigned OFF0, OFF1; __half2 W0H, W1H;                                     \
    {                                                                          \
        const float wk  = ws[(kk)];                                            \
        const float2 fk = sflow[(kk) * 64 + px];                               \
        const float ix = fmaf(-(W_DIM * 0.5f), fk.x, Ax);                      \
        const float iy = fmaf(-(H_DIM * 0.5f), fk.y, Ay);                      \
        const int x0 = __float2int_rd(ix);                                     \
        const int y0 = __float2int_rd(iy);                                     \
        const float wx = ix - (float)x0;                                       \
        const float wy = iy - (float)y0;                                       \
        const int x   = (x0 + xh) & (W_DIM - 1);                               \
        const int y0c = min(max(y0, 0), H_DIM - 1);                            \
        const int y1c = min(max(y0 + 1, 0), H_DIM - 1);                        \
        const float xw = fmaf(sx, wx, cx);                                     \
        const float tw = wk * xw;                                              \
        const float w1 = tw * wy;                                              \
        const float w0 = tw - w1;                                              \
        W0H = __float2half2_rn(w0);                                            \
        W1H = __float2half2_rn(w1);                                            \
        const unsigned ox = (unsigned)x << 5;                                  \
        OFF0 = ox + ((unsigned)y0c << 13);                                     \
        OFF1 = ox + ((unsigned)y1c << 13);                                     \
    }

#define BODY1(kk, GB)                                                          \
    {                                                                          \
        COORDS(kk, o0, o1, w0h, w1h);                                          \
        const uint4 u0 = *reinterpret_cast<const uint4*>((GB) + o0);           \
        const uint4 u1 = *reinterpret_cast<const uint4*>((GB) + o1);           \
        const __half2* h0 = reinterpret_cast<const __half2*>(&u0);             \
        const __half2* h1 = reinterpret_cast<const __half2*>(&u1);             \
        _Pragma("unroll")                                                      \
        for (int j = 0; j < 4; j++) {                                          \
            __half2 s = __hmul2(h0[j], w0h);                                   \
            s = __hfma2(h1[j], w1h, s);                                        \
            const float2 f = __half22float2(s);                                \
            acc[2 * j + 0] += f.x;                                             \
            acc[2 * j + 1] += f.y;                                             \
        }                                                                      \
    }

    // two k's at frames GB, GB+FRAME_BYTES: fp16 pair-accumulation
#define BODY2(kk, GB)                                                          \
    {                                                                          \
        COORDS((kk) + 0, a0, a1, aw0, aw1);                                    \
        const uint4 ua0 = *reinterpret_cast<const uint4*>((GB) + a0);          \
        const uint4 ua1 = *reinterpret_cast<const uint4*>((GB) + a1);          \
        COORDS((kk) + 1, b0, b1, bw0, bw1);                                    \
        const uint4 ub0 = *reinterpret_cast<const uint4*>((GB) + FRAME_BYTES + b0); \
        const uint4 ub1 = *reinterpret_cast<const uint4*>((GB) + FRAME_BYTES + b1); \
        const __half2* ha0 = reinterpret_cast<const __half2*>(&ua0);           \
        const __half2* ha1 = reinterpret_cast<const __half2*>(&ua1);           \
        const __half2* hb0 = reinterpret_cast<const __half2*>(&ub0);           \
        const __half2* hb1 = reinterpret_cast<const __half2*>(&ub1);           \
        _Pragma("unroll")                                                      \
        for (int j = 0; j < 4; j++) {                                          \
            __half2 s = __hmul2(ha0[j], aw0);                                  \
            s = __hfma2(ha1[j], aw1, s);                                       \
            s = __hfma2(hb0[j], bw0, s);                                       \
            s = __hfma2(hb1[j], bw1, s);                                       \
            const float2 f = __half22float2(s);                                \
            acc[2 * j + 0] += f.x;                                             \
            acc[2 * j + 1] += f.y;                                             \
        }                                                                      \
    }

    // gather loop over k = 0..t-1 (k == t handled as exact identity below)
    int k = 0;
#pragma unroll 2
    for (; k + 1 < t; k += 2) {
        BODY2(k, gbase);
        gbase += 2 * FRAME_BYTES;
    }
    if (k < t) BODY1(k, gbase);
#undef BODY2
#undef BODY1
#undef COORDS

    // merge x-halves: partner lane differs in bit 1 of tid
#pragma unroll
    for (int j = 0; j < 8; j++)
        acc[j] += __shfl_xor_sync(0xffffffffu, acc[j], 2);

    // diagonal term (k == t): identity sample from fp16 scratch, weight 1.
    // lane's 4 channels live at byte offset p*32 + ch*16 + xh*8 in frame t;
    // 32 lanes tile 256B contiguous -> 2 L1 lines per warp.
    const uint2 dg = *reinterpret_cast<const uint2*>(
        reinterpret_cast<const char*>(g_imgT) +
        (unsigned)t * FRAME_BYTES + ((unsigned)p << 5) +
        (unsigned)(ch * 16 + xh * 8));
    const float2 d0 = __half22float2(*reinterpret_cast<const __half2*>(&dg.x));
    const float2 d1 = __half22float2(*reinterpret_cast<const __half2*>(&dg.y));

    // each lane writes 4 channels: [ch*8 + xh*4, +4)
    const int cbase = (t * C_CH + ch * 8 + xh * 4) * HW + p;
    out[cbase + 0 * HW] = acc[xh * 4 + 0] + d0.x;
    out[cbase + 1 * HW] = acc[xh * 4 + 1] + d0.y;
    out[cbase + 2 * HW] = acc[xh * 4 + 2] + d1.x;
    out[cbase + 3 * HW] = acc[xh * 4 + 3] + d1.y;
}

extern "C" void kernel_launch(void* const* d_in, const int* in_sizes, int n_in,
                              void* d_out, int out_size) {
    const float* img      = (const float*)d_in[0];  // (1,16,16,128,256)
    const float* cum_flow = (const float*)d_in[1];  // (1,16,2,128,256)
    const float* mask     = (const float*)d_in[2];  // (16,16)
    const float* dist     = (const float*)d_in[3];  // (16,16)
    float* out            = (float*)d_out;          // (1,16,16,128,256)

    prep_kernel<<<L_FRAMES * H_DIM, W_DIM>>>(img);

    sample_kernel<<<HW / 64 * L_FRAMES, 256>>>(cum_flow, mask, dist, out);
}

// round 17
// speedup vs baseline: 1.0814x; 1.0335x over previous
#include <cuda_runtime.h>
#include <cuda_fp16.h>

#define L_FRAMES 16
#define C_CH     16
#define H_DIM    128
#define W_DIM    256
#define HW       (H_DIM * W_DIM)
#define DECAY_F  0.1f
#define FRAME_BYTES (HW * 32)          // one fp16 channel-last frame = 1 MB

// Channel-last fp16 scratch: [k][h][w][c], 16 MB (single copy)
__device__ __half g_imgT[L_FRAMES * HW * C_CH];

// ---------------------------------------------------------------------------
// Prep: transpose img [k][c][h][w] fp32 -> [k][h][w][c] fp16.
// ---------------------------------------------------------------------------
__global__ void prep_kernel(const float* __restrict__ img) {
    const int kh = blockIdx.x;          // k*H + h
    const int w  = threadIdx.x;         // 0..255
    const int k  = kh >> 7;
    const int h  = kh & (H_DIM - 1);

    __half2 v[8];
#pragma unroll
    for (int c = 0; c < 8; c++) {
        float a = img[((k * C_CH + 2 * c + 0) * H_DIM + h) * W_DIM + w];
        float b = img[((k * C_CH + 2 * c + 1) * H_DIM + h) * W_DIM + w];
        v[c] = __floats2half2_rn(a, b);
    }
    uint4* dst = reinterpret_cast<uint4*>(&g_imgT[((size_t)kh * W_DIM + w) * C_CH]);
    dst[0] = *reinterpret_cast<const uint4*>(&v[0]);
    dst[1] = *reinterpret_cast<const uint4*>(&v[4]);
}

// ---------------------------------------------------------------------------
// Warped accumulation. Flat grid 8192: t = bx & 15, pixel block = bx >> 4.
// 4 lanes per pixel: ch = sub&1 (16B channel half), xh = sub>>1 (x tap).
// k == t is the identity term (exact position, weight 1): read directly from
// the fp16 scratch at slot p (coalesced, 2 lines/warp) and folded into the
// store — the gather loop runs only k = 0..t-1.
// __launch_bounds__(256, 6): cap regs at 42 (natural is 43) so 6 blocks/SM
// fit — a 1-register squeeze, not the 8-reg spill-inducing caps of R10/R13.
// ---------------------------------------------------------------------------
__global__ void __launch_bounds__(256, 6) sample_kernel(
    const float* __restrict__ cum_flow,   // [k][2][h][w]
    const float* __restrict__ mask,       // [t][k]
    const float* __restrict__ dist,       // [t][k]
    float* __restrict__ out)              // [t][c][h][w]
{
    const int t  = blockIdx.x & 15;
    const int p0 = (blockIdx.x >> 4) << 6;

    __shared__ float  ws[L_FRAMES];
    __shared__ float2 sflow[L_FRAMES * 64];   // [k][px], 8 KB

    if (threadIdx.x < L_FRAMES) {
        int i = t * L_FRAMES + threadIdx.x;
        ws[threadIdx.x] = mask[i] * expf(-DECAY_F * dist[i]);
    }
#pragma unroll
    for (int i = 0; i < 4; i++) {
        const int idx = threadIdx.x + i * 256;      // k*64 + px
        const int kk  = idx >> 6;
        const int px  = idx & 63;
        const float fx = cum_flow[(kk * 2 + 0) * HW + p0 + px];
        const float fy = cum_flow[(kk * 2 + 1) * HW + p0 + px];
        sflow[idx] = make_float2(fx, fy);
    }
    __syncthreads();

    const int tid = threadIdx.x;
    const int sub = tid & 3;
    const int ch  = sub & 1;        // channel half: channels [ch*8, ch*8+8)
    const int xh  = sub >> 1;       // x tap: 0 -> x0, 1 -> x0+1
    const int px  = tid >> 2;       // pixel-in-block 0..63
    const int p   = p0 + px;
    const int h   = p >> 8;
    const int w   = p & (W_DIM - 1);

    const float2 ft = sflow[t * 64 + px];

    const float base_x = (float)w * (2.0f / W_DIM) - 1.0f + (1.0f / W_DIM);
    const float base_y = (float)h * (2.0f / H_DIM) - 1.0f + (1.0f / H_DIM);
    const float Ax = (base_x + ft.x + 1.0f) * (W_DIM * 0.5f) - 0.5f;
    const float Ay = (base_y + ft.y + 1.0f) * (H_DIM * 0.5f) - 0.5f;

    const float sx = xh ? 1.0f : -1.0f;
    const float cx = xh ? 0.0f : 1.0f;

    float acc[8];
#pragma unroll
    for (int j = 0; j < 8; j++) acc[j] = 0.0f;

    const char* __restrict__ gbase =
        reinterpret_cast<const char*>(g_imgT) + ch * 16;

    // offsets within the CURRENT frame only (no k term)
#define COORDS(kk, OFF0, OFF1, W0H, W1H)                                       \
    unsigned OFF0, OFF1; __half2 W0H, W1H;                                     \
    {                                                                          \
        const float wk  = ws[(kk)];                                            \
        const float2 fk = sflow[(kk) * 64 + px];                               \
        const float ix = fmaf(-(W_DIM * 0.5f), fk.x, Ax);                      \
        const float iy = fmaf(-(H_DIM * 0.5f), fk.y, Ay);                      \
        const int x0 = __float2int_rd(ix);                                     \
        const int y0 = __float2int_rd(iy);                                     \
        const float wx = ix - (float)x0;                                       \
        const float wy = iy - (float)y0;                                       \
        const int x   = (x0 + xh) & (W_DIM - 1);                               \
        const int y0c = min(max(y0, 0), H_DIM - 1);                            \
        const int y1c = min(max(y0 + 1, 0), H_DIM - 1);                        \
        const float xw = fmaf(sx, wx, cx);                                     \
        const float tw = wk * xw;                                              \
        const float w1 = tw * wy;                                              \
        const float w0 = tw - w1;                                              \
        W0H = __float2half2_rn(w0);                                            \
        W1H = __float2half2_rn(w1);                                            \
        const unsigned ox = (unsigned)x << 5;                                  \
        OFF0 = ox + ((unsigned)y0c << 13);                                     \
        OFF1 = ox + ((unsigned)y1c << 13);                                     \
    }

#define BODY1(kk, GB)                                                          \
    {                                                                          \
        COORDS(kk, o0, o1, w0h, w1h);                                          \
        const uint4 u0 = *reinterpret_cast<const uint4*>((GB) + o0);           \
        const uint4 u1 = *reinterpret_cast<const uint4*>((GB) + o1);           \
        const __half2* h0 = reinterpret_cast<const __half2*>(&u0);             \
        const __half2* h1 = reinterpret_cast<const __half2*>(&u1);             \
        _Pragma("unroll")                                                      \
        for (int j = 0; j < 4; j++) {                                          \
            __half2 s = __hmul2(h0[j], w0h);                                   \
            s = __hfma2(h1[j], w1h, s);                                        \
            const float2 f = __half22float2(s);                                \
            acc[2 * j + 0] += f.x;                                             \
            acc[2 * j + 1] += f.y;                                             \
        }                                                                      \
    }

    // two k's at frames GB, GB+FRAME_BYTES: fp16 pair-accumulation
#define BODY2(kk, GB)                                                          \
    {                                                                          \
        COORDS((kk) + 0, a0, a1, aw0, aw1);                                    \
        const uint4 ua0 = *reinterpret_cast<const uint4*>((GB) + a0);          \
        const uint4 ua1 = *reinterpret_cast<const uint4*>((GB) + a1);          \
        COORDS((kk) + 1, b0, b1, bw0, bw1);                                    \
        const uint4 ub0 = *reinterpret_cast<const uint4*>((GB) + FRAME_BYTES + b0); \
        const uint4 ub1 = *reinterpret_cast<const uint4*>((GB) + FRAME_BYTES + b1); \
        const __half2* ha0 = reinterpret_cast<const __half2*>(&ua0);           \
        const __half2* ha1 = reinterpret_cast<const __half2*>(&ua1);           \
        const __half2* hb0 = reinterpret_cast<const __half2*>(&ub0);           \
        const __half2* hb1 = reinterpret_cast<const __half2*>(&ub1);           \
        _Pragma("unroll")                                                      \
        for (int j = 0; j < 4; j++) {                                          \
            __half2 s = __hmul2(ha0[j], aw0);                                  \
            s = __hfma2(ha1[j], aw1, s);                                       \
            s = __hfma2(hb0[j], bw0, s);                                       \
            s = __hfma2(hb1[j], bw1, s);                                       \
            const float2 f = __half22float2(s);                                \
            acc[2 * j + 0] += f.x;                                             \
            acc[2 * j + 1] += f.y;                                             \
        }                                                                      \
    }

    // gather loop over k = 0..t-1 (k == t handled as exact identity below)
    int k = 0;
#pragma unroll 2
    for (; k + 1 < t; k += 2) {
        BODY2(k, gbase);
        gbase += 2 * FRAME_BYTES;
    }
    if (k < t) BODY1(k, gbase);
#undef BODY2
#undef BODY1
#undef COORDS

    // merge x-halves: partner lane differs in bit 1 of tid
#pragma unroll
    for (int j = 0; j < 8; j++)
        acc[j] += __shfl_xor_sync(0xffffffffu, acc[j], 2);

    // diagonal term (k == t): identity sample from fp16 scratch, weight 1.
    // lane's 4 channels live at byte offset p*32 + ch*16 + xh*8 in frame t;
    // 32 lanes tile 256B contiguous -> 2 L1 lines per warp.
    const uint2 dg = *reinterpret_cast<const uint2*>(
        reinterpret_cast<const char*>(g_imgT) +
        (unsigned)t * FRAME_BYTES + ((unsigned)p << 5) +
        (unsigned)(ch * 16 + xh * 8));
    const float2 d0 = __half22float2(*reinterpret_cast<const __half2*>(&dg.x));
    const float2 d1 = __half22float2(*reinterpret_cast<const __half2*>(&dg.y));

    // each lane writes 4 channels: [ch*8 + xh*4, +4)
    const int cbase = (t * C_CH + ch * 8 + xh * 4) * HW + p;
    out[cbase + 0 * HW] = acc[xh * 4 + 0] + d0.x;
    out[cbase + 1 * HW] = acc[xh * 4 + 1] + d0.y;
    out[cbase + 2 * HW] = acc[xh * 4 + 2] + d1.x;
    out[cbase + 3 * HW] = acc[xh * 4 + 3] + d1.y;
}

extern "C" void kernel_launch(void* const* d_in, const int* in_sizes, int n_in,
                              void* d_out, int out_size) {
    const float* img      = (const float*)d_in[0];  // (1,16,16,128,256)
    const float* cum_flow = (const float*)d_in[1];  // (1,16,2,128,256)
    const float* mask     = (const float*)d_in[2];  // (16,16)
    const float* dist     = (const float*)d_in[3];  // (16,16)
    float* out            = (float*)d_out;          // (1,16,16,128,256)

    prep_kernel<<<L_FRAMES * H_DIM, W_DIM>>>(img);

    sample_kernel<<<HW / 64 * L_FRAMES, 256>>>(cum_flow, mask, dist, out);
}